// round 1
// baseline (speedup 1.0000x reference)
#include <cuda_runtime.h>
#include <cuda_bf16.h>
#include <math.h>

// Problem constants
#define NTOK   4096      // B*S = 2*2048
#define DMODEL 1024
#define DFF    4096
#define NHEAD  16
#define HD     64
#define SEQ    2048

// ---------------------------------------------------------------------------
// Scratch (static device globals; no runtime allocation allowed)
// ---------------------------------------------------------------------------
__device__ float g_q  [NTOK * DMODEL];
__device__ float g_k  [NTOK * DMODEL];
__device__ float g_v  [NTOK * DMODEL];
__device__ float g_ctx[NTOK * DMODEL];
__device__ float g_tmp[NTOK * DMODEL];
__device__ float g_x  [NTOK * DMODEL];
__device__ float g_ff [NTOK * DFF];

// ---------------------------------------------------------------------------
// SGEMM: C[M,N] = A[M,K] @ B[K,N] + bias[N], optional ReLU.
// Block tile 128x128, K-step 8, 256 threads, 8x8 per-thread microtile.
// All dims are multiples of 128 in this problem (no bounds checks).
// ---------------------------------------------------------------------------
template <bool RELU>
__global__ __launch_bounds__(256, 2)
void sgemm128(const float* __restrict__ A, const float* __restrict__ B,
              const float* __restrict__ bias, float* __restrict__ C,
              int M, int N, int K)
{
    __shared__ float As[8][128];
    __shared__ float Bs[8][128];

    const int tid = threadIdx.x;
    const int bm  = blockIdx.y * 128;
    const int bn  = blockIdx.x * 128;

    const int tx = tid & 15;        // 0..15 -> col group
    const int ty = tid >> 4;        // 0..15 -> row group

    // A tile load mapping: 128 rows x 8 cols, one float4 per thread
    const int arow = tid >> 1;             // 0..127
    const int acol = (tid & 1) << 2;       // 0 or 4
    // B tile load mapping: 8 rows x 128 cols, one float4 per thread
    const int brow = tid >> 5;             // 0..7
    const int bcol = (tid & 31) << 2;      // 0..124

    const float* Aptr = A + (size_t)(bm + arow) * K + acol;
    const float* Bptr = B + (size_t)brow * N + bn + bcol;

    float acc[8][8];
    #pragma unroll
    for (int i = 0; i < 8; i++)
        #pragma unroll
        for (int j = 0; j < 8; j++) acc[i][j] = 0.f;

    for (int k0 = 0; k0 < K; k0 += 8) {
        float4 a4 = *(const float4*)(Aptr + k0);
        float4 b4 = *(const float4*)(Bptr + (size_t)k0 * N);

        As[acol + 0][arow] = a4.x;
        As[acol + 1][arow] = a4.y;
        As[acol + 2][arow] = a4.z;
        As[acol + 3][arow] = a4.w;
        *(float4*)&Bs[brow][bcol] = b4;
        __syncthreads();

        #pragma unroll
        for (int kk = 0; kk < 8; kk++) {
            float af[8], bf[8];
            float4 t;
            t = *(const float4*)&As[kk][ty * 8];     af[0]=t.x; af[1]=t.y; af[2]=t.z; af[3]=t.w;
            t = *(const float4*)&As[kk][ty * 8 + 4]; af[4]=t.x; af[5]=t.y; af[6]=t.z; af[7]=t.w;
            t = *(const float4*)&Bs[kk][tx * 8];     bf[0]=t.x; bf[1]=t.y; bf[2]=t.z; bf[3]=t.w;
            t = *(const float4*)&Bs[kk][tx * 8 + 4]; bf[4]=t.x; bf[5]=t.y; bf[6]=t.z; bf[7]=t.w;
            #pragma unroll
            for (int i = 0; i < 8; i++)
                #pragma unroll
                for (int j = 0; j < 8; j++)
                    acc[i][j] = fmaf(af[i], bf[j], acc[i][j]);
        }
        __syncthreads();
    }

    // Epilogue: bias (+ReLU) and store
    float4 bv0 = *(const float4*)(bias + bn + tx * 8);
    float4 bv1 = *(const float4*)(bias + bn + tx * 8 + 4);
    #pragma unroll
    for (int i = 0; i < 8; i++) {
        float4 o0, o1;
        o0.x = acc[i][0] + bv0.x; o0.y = acc[i][1] + bv0.y;
        o0.z = acc[i][2] + bv0.z; o0.w = acc[i][3] + bv0.w;
        o1.x = acc[i][4] + bv1.x; o1.y = acc[i][5] + bv1.y;
        o1.z = acc[i][6] + bv1.z; o1.w = acc[i][7] + bv1.w;
        if (RELU) {
            o0.x = fmaxf(o0.x, 0.f); o0.y = fmaxf(o0.y, 0.f);
            o0.z = fmaxf(o0.z, 0.f); o0.w = fmaxf(o0.w, 0.f);
            o1.x = fmaxf(o1.x, 0.f); o1.y = fmaxf(o1.y, 0.f);
            o1.z = fmaxf(o1.z, 0.f); o1.w = fmaxf(o1.w, 0.f);
        }
        float* crow = C + (size_t)(bm + ty * 8 + i) * N + bn + tx * 8;
        *(float4*)(crow)     = o0;
        *(float4*)(crow + 4) = o1;
    }
}

// ---------------------------------------------------------------------------
// Flash attention (fp32, hd=64). Grid: (S/128, B*H). 128 threads/block,
// one query row per thread (q + o accumulator in registers).
// Q/K/V/O layouts: [B*S, D] with head h occupying cols [h*64, h*64+64).
// ---------------------------------------------------------------------------
__global__ __launch_bounds__(128, 2)
void flash_attn(const float* __restrict__ Q, const float* __restrict__ K,
                const float* __restrict__ V, float* __restrict__ O)
{
    const int bh = blockIdx.y;
    const int b  = bh >> 4;
    const int h  = bh & 15;
    const int q  = blockIdx.x * 128 + threadIdx.x;   // query position within seq

    const size_t base = (size_t)b * SEQ * DMODEL + (size_t)h * HD;

    // Load this thread's query row into registers
    float qr[HD];
    {
        const float4* qrow = (const float4*)(Q + base + (size_t)q * DMODEL);
        #pragma unroll
        for (int i = 0; i < 16; i++) {
            float4 t = qrow[i];
            qr[4*i+0] = t.x; qr[4*i+1] = t.y; qr[4*i+2] = t.z; qr[4*i+3] = t.w;
        }
    }

    float o[HD];
    #pragma unroll
    for (int d = 0; d < HD; d++) o[d] = 0.f;
    float m = -1e30f, l = 0.f;

    __shared__ float4 Ks[32][16];
    __shared__ float4 Vs[32][16];

    const float scale = 0.125f;   // 1/sqrt(64)

    const int lr  = threadIdx.x >> 2;        // 0..31 tile row to load
    const int lc  = (threadIdx.x & 3) << 2;  // 0,4,8,12 float4 col base

    for (int kt = 0; kt < SEQ / 32; kt++) {
        const float4* krow = (const float4*)(K + base + (size_t)(kt * 32 + lr) * DMODEL);
        const float4* vrow = (const float4*)(V + base + (size_t)(kt * 32 + lr) * DMODEL);
        #pragma unroll
        for (int i = 0; i < 4; i++) {
            Ks[lr][lc + i] = krow[lc + i];
            Vs[lr][lc + i] = vrow[lc + i];
        }
        __syncthreads();

        float s[32];
        float tmax = -1e30f;
        #pragma unroll
        for (int j = 0; j < 32; j++) {
            float acc = 0.f;
            #pragma unroll
            for (int d = 0; d < 16; d++) {
                float4 k4 = Ks[j][d];
                acc = fmaf(qr[4*d+0], k4.x, acc);
                acc = fmaf(qr[4*d+1], k4.y, acc);
                acc = fmaf(qr[4*d+2], k4.z, acc);
                acc = fmaf(qr[4*d+3], k4.w, acc);
            }
            s[j] = acc * scale;
            tmax = fmaxf(tmax, s[j]);
        }

        float mnew = fmaxf(m, tmax);
        float corr = __expf(m - mnew);
        l *= corr;
        #pragma unroll
        for (int d = 0; d < HD; d++) o[d] *= corr;

        #pragma unroll
        for (int j = 0; j < 32; j++) {
            float p = __expf(s[j] - mnew);
            l += p;
            #pragma unroll
            for (int d = 0; d < 16; d++) {
                float4 v4 = Vs[j][d];
                o[4*d+0] = fmaf(p, v4.x, o[4*d+0]);
                o[4*d+1] = fmaf(p, v4.y, o[4*d+1]);
                o[4*d+2] = fmaf(p, v4.z, o[4*d+2]);
                o[4*d+3] = fmaf(p, v4.w, o[4*d+3]);
            }
        }
        m = mnew;
        __syncthreads();
    }

    const float inv = 1.0f / l;
    float4* orow = (float4*)(O + base + (size_t)q * DMODEL);
    #pragma unroll
    for (int i = 0; i < 16; i++) {
        float4 t;
        t.x = o[4*i+0] * inv; t.y = o[4*i+1] * inv;
        t.z = o[4*i+2] * inv; t.w = o[4*i+3] * inv;
        orow[i] = t;
    }
}

// ---------------------------------------------------------------------------
// Fused residual add + LayerNorm over D=1024. One block (256 threads) per row.
// out[row] = LN(A[row] + Bv[row]) * g + be
// ---------------------------------------------------------------------------
__global__ __launch_bounds__(256)
void add_ln(const float* __restrict__ A, const float* __restrict__ Bv,
            const float* __restrict__ g, const float* __restrict__ be,
            float* __restrict__ out)
{
    const int row = blockIdx.x;
    const int tid = threadIdx.x;

    const float4 a4 = ((const float4*)(A  + (size_t)row * DMODEL))[tid];
    const float4 b4 = ((const float4*)(Bv + (size_t)row * DMODEL))[tid];
    float4 v;
    v.x = a4.x + b4.x; v.y = a4.y + b4.y; v.z = a4.z + b4.z; v.w = a4.w + b4.w;

    float s  = v.x + v.y + v.z + v.w;
    float ss = v.x*v.x + v.y*v.y + v.z*v.z + v.w*v.w;

    #pragma unroll
    for (int ofs = 16; ofs > 0; ofs >>= 1) {
        s  += __shfl_xor_sync(0xFFFFFFFFu, s,  ofs);
        ss += __shfl_xor_sync(0xFFFFFFFFu, ss, ofs);
    }

    __shared__ float shs[8], shss[8];
    const int w = tid >> 5;
    if ((tid & 31) == 0) { shs[w] = s; shss[w] = ss; }
    __syncthreads();
    if (tid < 32) {
        float s2  = (tid < 8) ? shs[tid]  : 0.f;
        float ss2 = (tid < 8) ? shss[tid] : 0.f;
        #pragma unroll
        for (int ofs = 4; ofs > 0; ofs >>= 1) {
            s2  += __shfl_xor_sync(0xFFFFFFFFu, s2,  ofs);
            ss2 += __shfl_xor_sync(0xFFFFFFFFu, ss2, ofs);
        }
        if (tid == 0) { shs[0] = s2; shss[0] = ss2; }
    }
    __syncthreads();

    const float mu  = shs[0]  * (1.f / DMODEL);
    const float var = shss[0] * (1.f / DMODEL) - mu * mu;
    const float inv = rsqrtf(var + 1e-5f);

    const float4 gv = ((const float4*)g)[tid];
    const float4 bb = ((const float4*)be)[tid];
    float4 o;
    o.x = (v.x - mu) * inv * gv.x + bb.x;
    o.y = (v.y - mu) * inv * gv.y + bb.y;
    o.z = (v.z - mu) * inv * gv.z + bb.z;
    o.w = (v.w - mu) * inv * gv.w + bb.w;
    ((float4*)(out + (size_t)row * DMODEL))[tid] = o;
}

// ---------------------------------------------------------------------------
// Launch
// ---------------------------------------------------------------------------
extern "C" void kernel_launch(void* const* d_in, const int* in_sizes, int n_in,
                              void* d_out, int out_size)
{
    const float* src  = (const float*)d_in[0];
    const float* Wq   = (const float*)d_in[1];
    const float* bq   = (const float*)d_in[2];
    const float* Wk   = (const float*)d_in[3];
    const float* bk   = (const float*)d_in[4];
    const float* Wv   = (const float*)d_in[5];
    const float* bv   = (const float*)d_in[6];
    const float* Wo   = (const float*)d_in[7];
    const float* bo   = (const float*)d_in[8];
    const float* W1   = (const float*)d_in[9];
    const float* b1   = (const float*)d_in[10];
    const float* W2   = (const float*)d_in[11];
    const float* b2   = (const float*)d_in[12];
    const float* ln1g = (const float*)d_in[13];
    const float* ln1b = (const float*)d_in[14];
    const float* ln2g = (const float*)d_in[15];
    const float* ln2b = (const float*)d_in[16];
    float* out = (float*)d_out;

    float *pq, *pk, *pv, *pctx, *ptmp, *px, *pff;
    cudaGetSymbolAddress((void**)&pq,   g_q);
    cudaGetSymbolAddress((void**)&pk,   g_k);
    cudaGetSymbolAddress((void**)&pv,   g_v);
    cudaGetSymbolAddress((void**)&pctx, g_ctx);
    cudaGetSymbolAddress((void**)&ptmp, g_tmp);
    cudaGetSymbolAddress((void**)&px,   g_x);
    cudaGetSymbolAddress((void**)&pff,  g_ff);

    dim3 blk(256);

    // QKV projections
    {
        dim3 grid(DMODEL / 128, NTOK / 128);
        sgemm128<false><<<grid, blk>>>(src, Wq, bq, pq, NTOK, DMODEL, DMODEL);
        sgemm128<false><<<grid, blk>>>(src, Wk, bk, pk, NTOK, DMODEL, DMODEL);
        sgemm128<false><<<grid, blk>>>(src, Wv, bv, pv, NTOK, DMODEL, DMODEL);
    }

    // Attention
    {
        dim3 grid(SEQ / 128, 2 * NHEAD);
        flash_attn<<<grid, dim3(128)>>>(pq, pk, pv, pctx);
    }

    // Output projection + LN1
    {
        dim3 grid(DMODEL / 128, NTOK / 128);
        sgemm128<false><<<grid, blk>>>(pctx, Wo, bo, ptmp, NTOK, DMODEL, DMODEL);
        add_ln<<<NTOK, 256>>>(src, ptmp, ln1g, ln1b, px);
    }

    // FFN
    {
        dim3 grid1(DFF / 128, NTOK / 128);
        sgemm128<true><<<grid1, blk>>>(px, W1, b1, pff, NTOK, DFF, DMODEL);
        dim3 grid2(DMODEL / 128, NTOK / 128);
        sgemm128<false><<<grid2, blk>>>(pff, W2, b2, ptmp, NTOK, DMODEL, DFF);
        add_ln<<<NTOK, 256>>>(px, ptmp, ln2g, ln2b, out);
    }
}

// round 3
// speedup vs baseline: 1.7056x; 1.7056x over previous
#include <cuda_runtime.h>
#include <cuda_bf16.h>
#include <math.h>
#include <stdint.h>

// Problem constants
#define NTOK   4096      // B*S = 2*2048
#define DMODEL 1024
#define DFF    4096
#define NHEAD  16
#define HD     64
#define SEQ    2048

// ---------------------------------------------------------------------------
// Scratch (static device globals; no runtime allocation allowed)
// ---------------------------------------------------------------------------
__device__ __align__(16) float g_qkv [NTOK * 3 * DMODEL];    // fused q|k|v, row stride 3072
__device__ __align__(16) float g_wqkvT[3 * DMODEL * DMODEL]; // [3072,1024] K-major
__device__ __align__(16) float g_woT [DMODEL * DMODEL];
__device__ __align__(16) float g_w1T [DFF * DMODEL];
__device__ __align__(16) float g_w2T [DMODEL * DFF];
__device__ __align__(16) float g_bqkv[3 * DMODEL];
__device__ __align__(16) float g_ctx [NTOK * DMODEL];
__device__ __align__(16) float g_tmp [NTOK * DMODEL];
__device__ __align__(16) float g_x   [NTOK * DMODEL];
__device__ __align__(16) float g_ff  [NTOK * DFF];

// ---------------------------------------------------------------------------
// PTX helpers (baseline sm_80+ features only — harness targets plain sm_103)
// ---------------------------------------------------------------------------
__device__ __forceinline__ uint32_t smem_u32(const void* p) {
    uint32_t a;
    asm("{ .reg .u64 t; cvta.to.shared.u64 t, %1; cvt.u32.u64 %0, t; }" : "=r"(a) : "l"(p));
    return a;
}
#define CP_ASYNC16(dst, src) \
    asm volatile("cp.async.cg.shared.global [%0], [%1], 16;" :: "r"(dst), "l"(src))
#define CP_COMMIT() asm volatile("cp.async.commit_group;" ::: "memory")
#define CP_WAIT(n)  asm volatile("cp.async.wait_group %0;" :: "n"(n) : "memory")

#define LDMATRIX_X4(r0, r1, r2, r3, addr) \
    asm volatile("ldmatrix.sync.aligned.m8n8.x4.shared.b16 {%0,%1,%2,%3}, [%4];" \
                 : "=r"(r0), "=r"(r1), "=r"(r2), "=r"(r3) : "r"(addr))

__device__ __forceinline__ uint32_t to_tf32(uint32_t bits) {
    uint32_t o;
    asm("cvt.rna.tf32.f32 %0, %1;" : "=r"(o) : "f"(__uint_as_float(bits)));
    return o;
}

#define MMA_TF32(c0, c1, c2, c3, a0, a1, a2, a3, b0, b1) \
    asm volatile("mma.sync.aligned.m16n8k8.row.col.f32.tf32.tf32.f32 " \
                 "{%0,%1,%2,%3}, {%4,%5,%6,%7}, {%8,%9}, {%0,%1,%2,%3};" \
                 : "+f"(c0), "+f"(c1), "+f"(c2), "+f"(c3) \
                 : "r"(a0), "r"(a1), "r"(a2), "r"(a3), "r"(b0), "r"(b1))

// ---------------------------------------------------------------------------
// tf32 tensor-core GEMM:  C[M,N] = A[M,K] @ BT[N,K]^T + bias[N], optional ReLU
// 128x128 block tile, K-chunk 32, 256 threads (8 warps, 2x4 warp grid,
// warp tile 64x32), 4-stage cp.async pipeline, xor-swizzled smem,
// ldmatrix.x4 fragment loads. All dims multiples of 128.
// ---------------------------------------------------------------------------
#define STAGES 4
#define STAGE_BYTES (2 * 128 * 32 * 4)    // A 16KB + B 16KB
#define SMEM_DYN (STAGES * STAGE_BYTES)   // 128KB

template <bool RELU>
__global__ __launch_bounds__(256, 1)
void gemm_mma(const float* __restrict__ A, const float* __restrict__ BT,
              const float* __restrict__ bias, float* __restrict__ C,
              int M, int N, int K)
{
    extern __shared__ char smem[];
    const uint32_t sbase = smem_u32(smem);
    const int tid  = threadIdx.x;
    const int wid  = tid >> 5;
    const int lane = tid & 31;
    const int warp_m = wid & 1;        // 0..1
    const int warp_n = wid >> 1;       // 0..3
    const int gid = lane >> 2;         // 0..7
    const int tg  = lane & 3;          // 0..3

    const int bm = blockIdx.y * 128;
    const int bn = blockIdx.x * 128;
    const int KT = K >> 5;

    // --- cp.async load mapping: thread -> (row, 4 consecutive 16B units) ---
    const int lrow  = tid >> 1;             // 0..127
    const int lunit = (tid & 1) * 4;        // 0 or 4
    const float* Ag = A  + (size_t)(bm + lrow) * K + lunit * 4;
    const float* Bg = BT + (size_t)(bn + lrow) * K + lunit * 4;
    uint32_t lsw[4];
    #pragma unroll
    for (int i = 0; i < 4; i++) {
        uint32_t off = lrow * 128 + (lunit + i) * 16;
        lsw[i] = off ^ ((off >> 3) & 0x70);
    }

    // --- ldmatrix address components (relative to stage A/B base) ---
    // A: m-tile i, group g = lane>>3: rows +8 for g odd, k +4 for g>=2
    uint32_t a_rel[4], a_xr[4];
    #pragma unroll
    for (int i = 0; i < 4; i++) {
        int r = warp_m * 64 + i * 16 + (lane & 7) + ((lane >> 3) & 1) * 8;
        a_rel[i] = r * 128;
        a_xr[i]  = (r & 7) << 4;
    }
    const uint32_t a_kb = ((lane >> 4) & 1) * 16;   // +4 tf32 cols for groups 2,3
    // B: pair j covers n8-tiles {2j,2j+1}: rows +8 for g>=2, k +4 for g odd
    uint32_t b_rel[2], b_xr[2];
    #pragma unroll
    for (int j = 0; j < 2; j++) {
        int r = warp_n * 32 + j * 16 + (lane & 7) + ((lane >> 4) & 1) * 8;
        b_rel[j] = r * 128;
        b_xr[j]  = (r & 7) << 4;
    }
    const uint32_t b_kb = ((lane >> 3) & 1) * 16;

    float acc[4][4][4];
    #pragma unroll
    for (int i = 0; i < 4; i++)
        #pragma unroll
        for (int t = 0; t < 4; t++)
            #pragma unroll
            for (int r = 0; r < 4; r++) acc[i][t][r] = 0.f;

    auto load_tile = [&](int s, int kt) {
        const uint32_t sA = sbase + s * STAGE_BYTES;
        const uint32_t sB = sA + 16384;
        const float* ar = Ag + kt * 32;
        const float* br = Bg + kt * 32;
        #pragma unroll
        for (int i = 0; i < 4; i++) CP_ASYNC16(sA + lsw[i], ar + i * 4);
        #pragma unroll
        for (int i = 0; i < 4; i++) CP_ASYNC16(sB + lsw[i], br + i * 4);
    };

    #pragma unroll
    for (int s = 0; s < STAGES - 1; s++) { load_tile(s, s); CP_COMMIT(); }

    for (int kt = 0; kt < KT; kt++) {
        const int cur = kt & (STAGES - 1);
        CP_WAIT(STAGES - 2);
        __syncthreads();

        // prefetch (overlaps with compute below)
        const int pf = kt + STAGES - 1;
        if (pf < KT) load_tile(pf & (STAGES - 1), pf);
        CP_COMMIT();

        const uint32_t sA = sbase + cur * STAGE_BYTES;
        const uint32_t sB = sA + 16384;

        #pragma unroll
        for (int ks = 0; ks < 4; ks++) {
            const uint32_t kso = ks * 32;
            uint32_t af[4][4];
            #pragma unroll
            for (int i = 0; i < 4; i++) {
                uint32_t r0, r1, r2, r3;
                uint32_t addr = sA + ((a_rel[i] + a_kb + kso) ^ a_xr[i]);
                LDMATRIX_X4(r0, r1, r2, r3, addr);
                af[i][0] = to_tf32(r0); af[i][1] = to_tf32(r1);
                af[i][2] = to_tf32(r2); af[i][3] = to_tf32(r3);
            }
            uint32_t bf[4][2];
            #pragma unroll
            for (int j = 0; j < 2; j++) {
                uint32_t r0, r1, r2, r3;
                uint32_t addr = sB + ((b_rel[j] + b_kb + kso) ^ b_xr[j]);
                LDMATRIX_X4(r0, r1, r2, r3, addr);
                bf[2*j+0][0] = to_tf32(r0); bf[2*j+0][1] = to_tf32(r1);
                bf[2*j+1][0] = to_tf32(r2); bf[2*j+1][1] = to_tf32(r3);
            }
            #pragma unroll
            for (int i = 0; i < 4; i++)
                #pragma unroll
                for (int t = 0; t < 4; t++)
                    MMA_TF32(acc[i][t][0], acc[i][t][1], acc[i][t][2], acc[i][t][3],
                             af[i][0], af[i][1], af[i][2], af[i][3],
                             bf[t][0], bf[t][1]);
        }
        __syncthreads();
    }

    // Epilogue: c0,c1 -> (row gid, cols 2tg..2tg+1); c2,c3 -> row gid+8
    #pragma unroll
    for (int i = 0; i < 4; i++) {
        const int row0 = bm + warp_m * 64 + i * 16 + gid;
        #pragma unroll
        for (int t = 0; t < 4; t++) {
            const int col = bn + warp_n * 32 + t * 8 + 2 * tg;
            const float2 bv = *(const float2*)(bias + col);
            float2 v0, v1;
            v0.x = acc[i][t][0] + bv.x; v0.y = acc[i][t][1] + bv.y;
            v1.x = acc[i][t][2] + bv.x; v1.y = acc[i][t][3] + bv.y;
            if (RELU) {
                v0.x = fmaxf(v0.x, 0.f); v0.y = fmaxf(v0.y, 0.f);
                v1.x = fmaxf(v1.x, 0.f); v1.y = fmaxf(v1.y, 0.f);
            }
            *(float2*)(C + (size_t)row0 * N + col)       = v0;
            *(float2*)(C + (size_t)(row0 + 8) * N + col) = v1;
        }
    }
}

// ---------------------------------------------------------------------------
// Transpose: out[n][k] = in[k][n].  in: [K,N], out: [N,K]. block (32,8).
// ---------------------------------------------------------------------------
__global__ __launch_bounds__(256)
void transpose_k(const float* __restrict__ in, float* __restrict__ out, int K, int N)
{
    __shared__ float tile[32][33];
    const int k0 = blockIdx.y * 32, n0 = blockIdx.x * 32;
    const int tx = threadIdx.x, ty = threadIdx.y;
    #pragma unroll
    for (int i = ty; i < 32; i += 8)
        tile[i][tx] = in[(size_t)(k0 + i) * N + n0 + tx];
    __syncthreads();
    #pragma unroll
    for (int i = ty; i < 32; i += 8)
        out[(size_t)(n0 + i) * K + k0 + tx] = tile[tx][i];
}

__global__ void concat_bias(const float* a, const float* b, const float* c, float* out)
{
    int i = blockIdx.x * 256 + threadIdx.x;
    if (i < DMODEL)            out[i] = a[i];
    else if (i < 2 * DMODEL)   out[i] = b[i - DMODEL];
    else if (i < 3 * DMODEL)   out[i] = c[i - 2 * DMODEL];
}

// ---------------------------------------------------------------------------
// Flash attention (fp32, hd=64). Grid: (S/128, B*H). 128 threads/block.
// ---------------------------------------------------------------------------
__global__ __launch_bounds__(128, 2)
void flash_attn(const float* __restrict__ Q, const float* __restrict__ K,
                const float* __restrict__ V, float* __restrict__ O,
                int qld, int old_)
{
    const int bh = blockIdx.y;
    const int b  = bh >> 4;
    const int h  = bh & 15;
    const int q  = blockIdx.x * 128 + threadIdx.x;

    const size_t basei = (size_t)b * SEQ * qld + (size_t)h * HD;
    const size_t baseo = (size_t)b * SEQ * old_ + (size_t)h * HD;

    float qr[HD];
    {
        const float4* qrow = (const float4*)(Q + basei + (size_t)q * qld);
        #pragma unroll
        for (int i = 0; i < 16; i++) {
            float4 t = qrow[i];
            qr[4*i+0] = t.x; qr[4*i+1] = t.y; qr[4*i+2] = t.z; qr[4*i+3] = t.w;
        }
    }

    float o[HD];
    #pragma unroll
    for (int d = 0; d < HD; d++) o[d] = 0.f;
    float m = -1e30f, l = 0.f;

    __shared__ float4 Ks[32][16];
    __shared__ float4 Vs[32][16];

    const float scale = 0.125f;
    const int lr = threadIdx.x >> 2;
    const int lc = (threadIdx.x & 3) << 2;

    for (int kt = 0; kt < SEQ / 32; kt++) {
        const float4* krow = (const float4*)(K + basei + (size_t)(kt * 32 + lr) * qld);
        const float4* vrow = (const float4*)(V + basei + (size_t)(kt * 32 + lr) * qld);
        #pragma unroll
        for (int i = 0; i < 4; i++) {
            Ks[lr][lc + i] = krow[lc + i];
            Vs[lr][lc + i] = vrow[lc + i];
        }
        __syncthreads();

        float s[32];
        float tmax = -1e30f;
        #pragma unroll
        for (int j = 0; j < 32; j++) {
            float acc = 0.f;
            #pragma unroll
            for (int d = 0; d < 16; d++) {
                float4 k4 = Ks[j][d];
                acc = fmaf(qr[4*d+0], k4.x, acc);
                acc = fmaf(qr[4*d+1], k4.y, acc);
                acc = fmaf(qr[4*d+2], k4.z, acc);
                acc = fmaf(qr[4*d+3], k4.w, acc);
            }
            s[j] = acc * scale;
            tmax = fmaxf(tmax, s[j]);
        }

        float mnew = fmaxf(m, tmax);
        float corr = __expf(m - mnew);
        l *= corr;
        #pragma unroll
        for (int d = 0; d < HD; d++) o[d] *= corr;

        #pragma unroll
        for (int j = 0; j < 32; j++) {
            float p = __expf(s[j] - mnew);
            l += p;
            #pragma unroll
            for (int d = 0; d < 16; d++) {
                float4 v4 = Vs[j][d];
                o[4*d+0] = fmaf(p, v4.x, o[4*d+0]);
                o[4*d+1] = fmaf(p, v4.y, o[4*d+1]);
                o[4*d+2] = fmaf(p, v4.z, o[4*d+2]);
                o[4*d+3] = fmaf(p, v4.w, o[4*d+3]);
            }
        }
        m = mnew;
        __syncthreads();
    }

    const float inv = 1.0f / l;
    float4* orow = (float4*)(O + baseo + (size_t)q * old_);
    #pragma unroll
    for (int i = 0; i < 16; i++) {
        float4 t;
        t.x = o[4*i+0] * inv; t.y = o[4*i+1] * inv;
        t.z = o[4*i+2] * inv; t.w = o[4*i+3] * inv;
        orow[i] = t;
    }
}

// ---------------------------------------------------------------------------
// Fused residual add + LayerNorm over D=1024. One block (256 threads) per row.
// ---------------------------------------------------------------------------
__global__ __launch_bounds__(256)
void add_ln(const float* __restrict__ A, const float* __restrict__ Bv,
            const float* __restrict__ g, const float* __restrict__ be,
            float* __restrict__ out)
{
    const int row = blockIdx.x;
    const int tid = threadIdx.x;

    const float4 a4 = ((const float4*)(A  + (size_t)row * DMODEL))[tid];
    const float4 b4 = ((const float4*)(Bv + (size_t)row * DMODEL))[tid];
    float4 v;
    v.x = a4.x + b4.x; v.y = a4.y + b4.y; v.z = a4.z + b4.z; v.w = a4.w + b4.w;

    float s  = v.x + v.y + v.z + v.w;
    float ss = v.x*v.x + v.y*v.y + v.z*v.z + v.w*v.w;

    #pragma unroll
    for (int ofs = 16; ofs > 0; ofs >>= 1) {
        s  += __shfl_xor_sync(0xFFFFFFFFu, s,  ofs);
        ss += __shfl_xor_sync(0xFFFFFFFFu, ss, ofs);
    }

    __shared__ float shs[8], shss[8];
    const int w = tid >> 5;
    if ((tid & 31) == 0) { shs[w] = s; shss[w] = ss; }
    __syncthreads();
    if (tid < 32) {
        float s2  = (tid < 8) ? shs[tid]  : 0.f;
        float ss2 = (tid < 8) ? shss[tid] : 0.f;
        #pragma unroll
        for (int ofs = 4; ofs > 0; ofs >>= 1) {
            s2  += __shfl_xor_sync(0xFFFFFFFFu, s2,  ofs);
            ss2 += __shfl_xor_sync(0xFFFFFFFFu, ss2, ofs);
        }
        if (tid == 0) { shs[0] = s2; shss[0] = ss2; }
    }
    __syncthreads();

    const float mu  = shs[0]  * (1.f / DMODEL);
    const float var = shss[0] * (1.f / DMODEL) - mu * mu;
    const float inv = rsqrtf(var + 1e-5f);

    const float4 gv = ((const float4*)g)[tid];
    const float4 bb = ((const float4*)be)[tid];
    float4 o;
    o.x = (v.x - mu) * inv * gv.x + bb.x;
    o.y = (v.y - mu) * inv * gv.y + bb.y;
    o.z = (v.z - mu) * inv * gv.z + bb.z;
    o.w = (v.w - mu) * inv * gv.w + bb.w;
    ((float4*)(out + (size_t)row * DMODEL))[tid] = o;
}

// ---------------------------------------------------------------------------
// Launch
// ---------------------------------------------------------------------------
extern "C" void kernel_launch(void* const* d_in, const int* in_sizes, int n_in,
                              void* d_out, int out_size)
{
    const float* src  = (const float*)d_in[0];
    const float* Wq   = (const float*)d_in[1];
    const float* bq   = (const float*)d_in[2];
    const float* Wk   = (const float*)d_in[3];
    const float* bk   = (const float*)d_in[4];
    const float* Wv   = (const float*)d_in[5];
    const float* bv   = (const float*)d_in[6];
    const float* Wo   = (const float*)d_in[7];
    const float* bo   = (const float*)d_in[8];
    const float* W1   = (const float*)d_in[9];
    const float* b1   = (const float*)d_in[10];
    const float* W2   = (const float*)d_in[11];
    const float* b2   = (const float*)d_in[12];
    const float* ln1g = (const float*)d_in[13];
    const float* ln1b = (const float*)d_in[14];
    const float* ln2g = (const float*)d_in[15];
    const float* ln2b = (const float*)d_in[16];
    float* out = (float*)d_out;

    float *pqkv, *pwqkvT, *pwoT, *pw1T, *pw2T, *pbqkv, *pctx, *ptmp, *px, *pff;
    cudaGetSymbolAddress((void**)&pqkv,   g_qkv);
    cudaGetSymbolAddress((void**)&pwqkvT, g_wqkvT);
    cudaGetSymbolAddress((void**)&pwoT,   g_woT);
    cudaGetSymbolAddress((void**)&pw1T,   g_w1T);
    cudaGetSymbolAddress((void**)&pw2T,   g_w2T);
    cudaGetSymbolAddress((void**)&pbqkv,  g_bqkv);
    cudaGetSymbolAddress((void**)&pctx,   g_ctx);
    cudaGetSymbolAddress((void**)&ptmp,   g_tmp);
    cudaGetSymbolAddress((void**)&px,     g_x);
    cudaGetSymbolAddress((void**)&pff,    g_ff);

    cudaFuncSetAttribute(gemm_mma<false>, cudaFuncAttributeMaxDynamicSharedMemorySize, SMEM_DYN);
    cudaFuncSetAttribute(gemm_mma<true>,  cudaFuncAttributeMaxDynamicSharedMemorySize, SMEM_DYN);

    // Weight transposes (to K-major [N, K]) + fused qkv bias
    {
        dim3 blk(32, 8);
        transpose_k<<<dim3(32, 32),  blk>>>(Wq, pwqkvT,                       DMODEL, DMODEL);
        transpose_k<<<dim3(32, 32),  blk>>>(Wk, pwqkvT + DMODEL * DMODEL,     DMODEL, DMODEL);
        transpose_k<<<dim3(32, 32),  blk>>>(Wv, pwqkvT + 2 * DMODEL * DMODEL, DMODEL, DMODEL);
        transpose_k<<<dim3(32, 32),  blk>>>(Wo, pwoT,  DMODEL, DMODEL);
        transpose_k<<<dim3(128, 32), blk>>>(W1, pw1T,  DMODEL, DFF);
        transpose_k<<<dim3(32, 128), blk>>>(W2, pw2T,  DFF,    DMODEL);
        concat_bias<<<12, 256>>>(bq, bk, bv, pbqkv);
    }

    // Fused QKV projection: [4096,1024] @ [1024,3072] -> [4096,3072]
    gemm_mma<false><<<dim3(3 * DMODEL / 128, NTOK / 128), 256, SMEM_DYN>>>(
        src, pwqkvT, pbqkv, pqkv, NTOK, 3 * DMODEL, DMODEL);

    // Attention over the fused buffer (q|k|v at col offsets 0/1024/2048, stride 3072)
    flash_attn<<<dim3(SEQ / 128, 2 * NHEAD), 128>>>(
        pqkv, pqkv + DMODEL, pqkv + 2 * DMODEL, pctx, 3 * DMODEL, DMODEL);

    // Output projection + LN1
    gemm_mma<false><<<dim3(DMODEL / 128, NTOK / 128), 256, SMEM_DYN>>>(
        pctx, pwoT, bo, ptmp, NTOK, DMODEL, DMODEL);
    add_ln<<<NTOK, 256>>>(src, ptmp, ln1g, ln1b, px);

    // FFN
    gemm_mma<true><<<dim3(DFF / 128, NTOK / 128), 256, SMEM_DYN>>>(
        px, pw1T, b1, pff, NTOK, DFF, DMODEL);
    gemm_mma<false><<<dim3(DMODEL / 128, NTOK / 128), 256, SMEM_DYN>>>(
        pff, pw2T, b2, ptmp, NTOK, DMODEL, DFF);
    add_ln<<<NTOK, 256>>>(px, ptmp, ln2g, ln2b, out);
}

// round 5
// speedup vs baseline: 2.7468x; 1.6105x over previous
#include <cuda_runtime.h>
#include <cuda_bf16.h>
#include <math.h>
#include <stdint.h>

// Problem constants
#define NTOK   4096      // B*S = 2*2048
#define DMODEL 1024
#define DFF    4096
#define NHEAD  16
#define HD     64
#define SEQ    2048
#define QLD    (3 * DMODEL)   // fused qkv row stride

// ---------------------------------------------------------------------------
// Scratch (static device globals; no runtime allocation allowed)
// ---------------------------------------------------------------------------
__device__ __align__(16) float g_qkv [NTOK * 3 * DMODEL];    // fused q|k|v
__device__ __align__(16) float g_vt  [32 * HD * SEQ];        // V^T per (b,h): [64][2048]
__device__ __align__(16) float g_wqkvT[3 * DMODEL * DMODEL]; // [3072,1024] K-major
__device__ __align__(16) float g_woT [DMODEL * DMODEL];
__device__ __align__(16) float g_w1T [DFF * DMODEL];
__device__ __align__(16) float g_w2T [DMODEL * DFF];
__device__ __align__(16) float g_bqkv[3 * DMODEL];
__device__ __align__(16) float g_ctx [NTOK * DMODEL];
__device__ __align__(16) float g_tmp [NTOK * DMODEL];
__device__ __align__(16) float g_x   [NTOK * DMODEL];
__device__ __align__(16) float g_ff  [NTOK * DFF];

// ---------------------------------------------------------------------------
// PTX helpers (baseline sm_80+ features only — harness targets plain sm_103)
// ---------------------------------------------------------------------------
__device__ __forceinline__ uint32_t smem_u32(const void* p) {
    uint32_t a;
    asm("{ .reg .u64 t; cvta.to.shared.u64 t, %1; cvt.u32.u64 %0, t; }" : "=r"(a) : "l"(p));
    return a;
}
#define CP_ASYNC16(dst, src) \
    asm volatile("cp.async.cg.shared.global [%0], [%1], 16;" :: "r"(dst), "l"(src))
#define CP_COMMIT() asm volatile("cp.async.commit_group;" ::: "memory")
#define CP_WAIT(n)  asm volatile("cp.async.wait_group %0;" :: "n"(n) : "memory")

#define LDMATRIX_X4(r0, r1, r2, r3, addr) \
    asm volatile("ldmatrix.sync.aligned.m8n8.x4.shared.b16 {%0,%1,%2,%3}, [%4];" \
                 : "=r"(r0), "=r"(r1), "=r"(r2), "=r"(r3) : "r"(addr))

__device__ __forceinline__ uint32_t to_tf32(uint32_t bits) {
    uint32_t o;
    asm("cvt.rna.tf32.f32 %0, %1;" : "=r"(o) : "f"(__uint_as_float(bits)));
    return o;
}
__device__ __forceinline__ uint32_t to_tf32f(float f) {
    uint32_t o;
    asm("cvt.rna.tf32.f32 %0, %1;" : "=r"(o) : "f"(f));
    return o;
}

#define MMA_TF32(c0, c1, c2, c3, a0, a1, a2, a3, b0, b1) \
    asm volatile("mma.sync.aligned.m16n8k8.row.col.f32.tf32.tf32.f32 " \
                 "{%0,%1,%2,%3}, {%4,%5,%6,%7}, {%8,%9}, {%0,%1,%2,%3};" \
                 : "+f"(c0), "+f"(c1), "+f"(c2), "+f"(c3) \
                 : "r"(a0), "r"(a1), "r"(a2), "r"(a3), "r"(b0), "r"(b1))

// ---------------------------------------------------------------------------
// tf32 tensor-core GEMM:  C[M,N] = A[M,K] @ BT[N,K]^T + bias[N], optional ReLU
// (unchanged from R3 — passing at rel_err 9e-5)
// ---------------------------------------------------------------------------
#define STAGES 4
#define STAGE_BYTES (2 * 128 * 32 * 4)
#define SMEM_DYN (STAGES * STAGE_BYTES)

template <bool RELU>
__global__ __launch_bounds__(256, 1)
void gemm_mma(const float* __restrict__ A, const float* __restrict__ BT,
              const float* __restrict__ bias, float* __restrict__ C,
              int M, int N, int K)
{
    extern __shared__ char smem[];
    const uint32_t sbase = smem_u32(smem);
    const int tid  = threadIdx.x;
    const int wid  = tid >> 5;
    const int lane = tid & 31;
    const int warp_m = wid & 1;
    const int warp_n = wid >> 1;
    const int gid = lane >> 2;
    const int tg  = lane & 3;

    const int bm = blockIdx.y * 128;
    const int bn = blockIdx.x * 128;
    const int KT = K >> 5;

    const int lrow  = tid >> 1;
    const int lunit = (tid & 1) * 4;
    const float* Ag = A  + (size_t)(bm + lrow) * K + lunit * 4;
    const float* Bg = BT + (size_t)(bn + lrow) * K + lunit * 4;
    uint32_t lsw[4];
    #pragma unroll
    for (int i = 0; i < 4; i++) {
        uint32_t off = lrow * 128 + (lunit + i) * 16;
        lsw[i] = off ^ ((off >> 3) & 0x70);
    }

    uint32_t a_rel[4], a_xr[4];
    #pragma unroll
    for (int i = 0; i < 4; i++) {
        int r = warp_m * 64 + i * 16 + (lane & 7) + ((lane >> 3) & 1) * 8;
        a_rel[i] = r * 128;
        a_xr[i]  = (r & 7) << 4;
    }
    const uint32_t a_kb = ((lane >> 4) & 1) * 16;
    uint32_t b_rel[2], b_xr[2];
    #pragma unroll
    for (int j = 0; j < 2; j++) {
        int r = warp_n * 32 + j * 16 + (lane & 7) + ((lane >> 4) & 1) * 8;
        b_rel[j] = r * 128;
        b_xr[j]  = (r & 7) << 4;
    }
    const uint32_t b_kb = ((lane >> 3) & 1) * 16;

    float acc[4][4][4];
    #pragma unroll
    for (int i = 0; i < 4; i++)
        #pragma unroll
        for (int t = 0; t < 4; t++)
            #pragma unroll
            for (int r = 0; r < 4; r++) acc[i][t][r] = 0.f;

    auto load_tile = [&](int s, int kt) {
        const uint32_t sA = sbase + s * STAGE_BYTES;
        const uint32_t sB = sA + 16384;
        const float* ar = Ag + kt * 32;
        const float* br = Bg + kt * 32;
        #pragma unroll
        for (int i = 0; i < 4; i++) CP_ASYNC16(sA + lsw[i], ar + i * 4);
        #pragma unroll
        for (int i = 0; i < 4; i++) CP_ASYNC16(sB + lsw[i], br + i * 4);
    };

    #pragma unroll
    for (int s = 0; s < STAGES - 1; s++) { load_tile(s, s); CP_COMMIT(); }

    for (int kt = 0; kt < KT; kt++) {
        const int cur = kt & (STAGES - 1);
        CP_WAIT(STAGES - 2);
        __syncthreads();

        const int pf = kt + STAGES - 1;
        if (pf < KT) load_tile(pf & (STAGES - 1), pf);
        CP_COMMIT();

        const uint32_t sA = sbase + cur * STAGE_BYTES;
        const uint32_t sB = sA + 16384;

        #pragma unroll
        for (int ks = 0; ks < 4; ks++) {
            const uint32_t kso = ks * 32;
            uint32_t af[4][4];
            #pragma unroll
            for (int i = 0; i < 4; i++) {
                uint32_t r0, r1, r2, r3;
                uint32_t addr = sA + ((a_rel[i] + a_kb + kso) ^ a_xr[i]);
                LDMATRIX_X4(r0, r1, r2, r3, addr);
                af[i][0] = to_tf32(r0); af[i][1] = to_tf32(r1);
                af[i][2] = to_tf32(r2); af[i][3] = to_tf32(r3);
            }
            uint32_t bf[4][2];
            #pragma unroll
            for (int j = 0; j < 2; j++) {
                uint32_t r0, r1, r2, r3;
                uint32_t addr = sB + ((b_rel[j] + b_kb + kso) ^ b_xr[j]);
                LDMATRIX_X4(r0, r1, r2, r3, addr);
                bf[2*j+0][0] = to_tf32(r0); bf[2*j+0][1] = to_tf32(r1);
                bf[2*j+1][0] = to_tf32(r2); bf[2*j+1][1] = to_tf32(r3);
            }
            #pragma unroll
            for (int i = 0; i < 4; i++)
                #pragma unroll
                for (int t = 0; t < 4; t++)
                    MMA_TF32(acc[i][t][0], acc[i][t][1], acc[i][t][2], acc[i][t][3],
                             af[i][0], af[i][1], af[i][2], af[i][3],
                             bf[t][0], bf[t][1]);
        }
        __syncthreads();
    }

    #pragma unroll
    for (int i = 0; i < 4; i++) {
        const int row0 = bm + warp_m * 64 + i * 16 + gid;
        #pragma unroll
        for (int t = 0; t < 4; t++) {
            const int col = bn + warp_n * 32 + t * 8 + 2 * tg;
            const float2 bv = *(const float2*)(bias + col);
            float2 v0, v1;
            v0.x = acc[i][t][0] + bv.x; v0.y = acc[i][t][1] + bv.y;
            v1.x = acc[i][t][2] + bv.x; v1.y = acc[i][t][3] + bv.y;
            if (RELU) {
                v0.x = fmaxf(v0.x, 0.f); v0.y = fmaxf(v0.y, 0.f);
                v1.x = fmaxf(v1.x, 0.f); v1.y = fmaxf(v1.y, 0.f);
            }
            *(float2*)(C + (size_t)row0 * N + col)       = v0;
            *(float2*)(C + (size_t)(row0 + 8) * N + col) = v1;
        }
    }
}

// ---------------------------------------------------------------------------
// Tensor-core flash attention (tf32 mma). 64 queries x 1 head per block.
// 4 warps (16 q-rows each). K-tile = 64 keys, double-buffered cp.async.
// Tile smem layout: 2 chunks of 8192B; chunk c = cols 32c..32c+31 (128B rows).
// ---------------------------------------------------------------------------
#define ATT_SMEM 65536   // 2 stages x (16KB K + 16KB VT); Q staged in stage1-K

__global__ __launch_bounds__(128, 1)
void flash_mma(const float* __restrict__ QKV, const float* __restrict__ VT,
               float* __restrict__ O)
{
    extern __shared__ char smem[];
    const uint32_t sbase = smem_u32(smem);
    const int tid  = threadIdx.x;
    const int wid  = tid >> 5;
    const int lane = tid & 31;
    const int gid  = lane >> 2;
    const int tg   = lane & 3;

    const int bh = blockIdx.y;
    const int b  = bh >> 4;
    const int h  = bh & 15;
    const int q0 = blockIdx.x * 64;

    const float* Qg  = QKV + (size_t)b * SEQ * QLD + h * HD;
    const float* Kg  = Qg + DMODEL;
    const float* VTg = VT + (size_t)bh * HD * SEQ;

    const uint32_t qreg = sbase + 32768;   // stage-1 K region reused for Q staging

    // ---- load mapping: tile 64 rows x 64 floats, 2 chunks of (64 x 32f) ----
    const int lrow = tid >> 1;             // 0..63
    const int lu0  = (tid & 1) * 8;        // units 0..7 or 8..15 (16B units)
    uint32_t lsw[8];
    #pragma unroll
    for (int i = 0; i < 8; i++) {
        int u = lu0 + i;                                  // 0..15
        uint32_t off = lrow * 128 + (u & 7) * 16;         // within 8KB chunk
        lsw[i] = (u >> 3) * 8192 + (off ^ ((off >> 3) & 0x70));
    }

    // ---- fragment addressing ----
    uint32_t aq_rel, aq_xr;
    {
        int r = wid * 16 + (lane & 7) + ((lane >> 3) & 1) * 8;
        aq_rel = r * 128;
        aq_xr  = (r & 7) << 4;
    }
    const uint32_t a_kb = ((lane >> 4) & 1) * 16;
    uint32_t b_rel[4], b_xr[4];
    #pragma unroll
    for (int j = 0; j < 4; j++) {
        int r = j * 16 + (lane & 7) + ((lane >> 4) & 1) * 8;
        b_rel[j] = r * 128;
        b_xr[j]  = (r & 7) << 4;
    }
    const uint32_t b_kb = ((lane >> 3) & 1) * 16;

    auto load_KV = [&](int stage, int kt) {
        const uint32_t sK = sbase + stage * 32768;
        const uint32_t sV = sK + 16384;
        const float* kr = Kg  + (size_t)(kt * 64 + lrow) * QLD + lu0 * 4;
        const float* vr = VTg + (size_t)lrow * SEQ + kt * 64 + lu0 * 4;
        #pragma unroll
        for (int i = 0; i < 8; i++) CP_ASYNC16(sK + lsw[i], kr + i * 4);
        #pragma unroll
        for (int i = 0; i < 8; i++) CP_ASYNC16(sV + lsw[i], vr + i * 4);
    };

    // ---- prologue: Q + tile 0 ----
    {
        const float* qr = Qg + (size_t)(q0 + lrow) * QLD + lu0 * 4;
        #pragma unroll
        for (int i = 0; i < 8; i++) CP_ASYNC16(qreg + lsw[i], qr + i * 4);
        load_KV(0, 0);
        CP_COMMIT();
        CP_WAIT(0);
        __syncthreads();
    }

    // extract Q fragments (8 ksteps over 64 dims)
    uint32_t qf[8][4];
    #pragma unroll
    for (int c = 0; c < 2; c++)
        #pragma unroll
        for (int ks = 0; ks < 4; ks++) {
            uint32_t r0, r1, r2, r3;
            uint32_t addr = qreg + c * 8192 + ((aq_rel + a_kb + ks * 32) ^ aq_xr);
            LDMATRIX_X4(r0, r1, r2, r3, addr);
            qf[c*4+ks][0] = to_tf32(r0); qf[c*4+ks][1] = to_tf32(r1);
            qf[c*4+ks][2] = to_tf32(r2); qf[c*4+ks][3] = to_tf32(r3);
        }
    __syncthreads();

    const int NT = SEQ / 64;
    load_KV(1, 1);
    CP_COMMIT();

    float o[8][4];
    #pragma unroll
    for (int t = 0; t < 8; t++)
        #pragma unroll
        for (int r = 0; r < 4; r++) o[t][r] = 0.f;
    float m0 = -1e30f, m1 = -1e30f, l0 = 0.f, l1 = 0.f;

    for (int kt = 0; kt < NT; kt++) {
        if (kt < NT - 1) { CP_WAIT(1); } else { CP_WAIT(0); }
        __syncthreads();
        const uint32_t sK = sbase + (kt & 1) * 32768;
        const uint32_t sV = sK + 16384;

        // ---- S = Q @ K^T ----
        float s[8][4];
        #pragma unroll
        for (int t = 0; t < 8; t++)
            #pragma unroll
            for (int r = 0; r < 4; r++) s[t][r] = 0.f;

        #pragma unroll
        for (int c = 0; c < 2; c++)
            #pragma unroll
            for (int ks = 0; ks < 4; ks++) {
                uint32_t bf[8][2];
                #pragma unroll
                for (int j = 0; j < 4; j++) {
                    uint32_t r0, r1, r2, r3;
                    uint32_t addr = sK + c * 8192 + ((b_rel[j] + b_kb + ks * 32) ^ b_xr[j]);
                    LDMATRIX_X4(r0, r1, r2, r3, addr);
                    bf[2*j+0][0] = to_tf32(r0); bf[2*j+0][1] = to_tf32(r1);
                    bf[2*j+1][0] = to_tf32(r2); bf[2*j+1][1] = to_tf32(r3);
                }
                const uint32_t* aq = qf[c*4+ks];
                #pragma unroll
                for (int t = 0; t < 8; t++)
                    MMA_TF32(s[t][0], s[t][1], s[t][2], s[t][3],
                             aq[0], aq[1], aq[2], aq[3], bf[t][0], bf[t][1]);
            }

        // ---- online softmax ----
        float tmax0 = -1e30f, tmax1 = -1e30f;
        #pragma unroll
        for (int t = 0; t < 8; t++) {
            s[t][0] *= 0.125f; s[t][1] *= 0.125f; s[t][2] *= 0.125f; s[t][3] *= 0.125f;
            tmax0 = fmaxf(tmax0, fmaxf(s[t][0], s[t][1]));
            tmax1 = fmaxf(tmax1, fmaxf(s[t][2], s[t][3]));
        }
        tmax0 = fmaxf(tmax0, __shfl_xor_sync(0xffffffffu, tmax0, 1));
        tmax0 = fmaxf(tmax0, __shfl_xor_sync(0xffffffffu, tmax0, 2));
        tmax1 = fmaxf(tmax1, __shfl_xor_sync(0xffffffffu, tmax1, 1));
        tmax1 = fmaxf(tmax1, __shfl_xor_sync(0xffffffffu, tmax1, 2));

        const float mnew0 = fmaxf(m0, tmax0);
        const float mnew1 = fmaxf(m1, tmax1);
        const float corr0 = __expf(m0 - mnew0);
        const float corr1 = __expf(m1 - mnew1);

        float rs0 = 0.f, rs1 = 0.f;
        #pragma unroll
        for (int t = 0; t < 8; t++) {
            s[t][0] = __expf(s[t][0] - mnew0);
            s[t][1] = __expf(s[t][1] - mnew0);
            s[t][2] = __expf(s[t][2] - mnew1);
            s[t][3] = __expf(s[t][3] - mnew1);
            rs0 += s[t][0] + s[t][1];
            rs1 += s[t][2] + s[t][3];
        }
        rs0 += __shfl_xor_sync(0xffffffffu, rs0, 1);
        rs0 += __shfl_xor_sync(0xffffffffu, rs0, 2);
        rs1 += __shfl_xor_sync(0xffffffffu, rs1, 1);
        rs1 += __shfl_xor_sync(0xffffffffu, rs1, 2);

        l0 = l0 * corr0 + rs0;
        l1 = l1 * corr1 + rs1;
        #pragma unroll
        for (int t = 0; t < 8; t++) {
            o[t][0] *= corr0; o[t][1] *= corr0;
            o[t][2] *= corr1; o[t][3] *= corr1;
        }
        m0 = mnew0; m1 = mnew1;

        // ---- ctx += P @ V  (V^T in smem, B-operand identical to K path) ----
        #pragma unroll
        for (int ks = 0; ks < 8; ks++) {
            const int src0 = tg >> 1, src1 = src0 + 2;
            float v00 = __shfl_sync(0xffffffffu, s[ks][0], src0, 4);
            float v01 = __shfl_sync(0xffffffffu, s[ks][1], src0, 4);
            float v20 = __shfl_sync(0xffffffffu, s[ks][0], src1, 4);
            float v21 = __shfl_sync(0xffffffffu, s[ks][1], src1, 4);
            float v10 = __shfl_sync(0xffffffffu, s[ks][2], src0, 4);
            float v11 = __shfl_sync(0xffffffffu, s[ks][3], src0, 4);
            float v30 = __shfl_sync(0xffffffffu, s[ks][2], src1, 4);
            float v31 = __shfl_sync(0xffffffffu, s[ks][3], src1, 4);
            const bool oddc = (tg & 1);
            uint32_t a0 = to_tf32f(oddc ? v01 : v00);   // P[gid][tg]
            uint32_t a1 = to_tf32f(oddc ? v11 : v10);   // P[gid+8][tg]
            uint32_t a2 = to_tf32f(oddc ? v21 : v20);   // P[gid][tg+4]
            uint32_t a3 = to_tf32f(oddc ? v31 : v30);   // P[gid+8][tg+4]

            uint32_t bf[8][2];
            const uint32_t vbase = sV + (ks >> 2) * 8192;
            const uint32_t kso = (ks & 3) * 32;
            #pragma unroll
            for (int j = 0; j < 4; j++) {
                uint32_t r0, r1, r2, r3;
                uint32_t addr = vbase + ((b_rel[j] + b_kb + kso) ^ b_xr[j]);
                LDMATRIX_X4(r0, r1, r2, r3, addr);
                bf[2*j+0][0] = to_tf32(r0); bf[2*j+0][1] = to_tf32(r1);
                bf[2*j+1][0] = to_tf32(r2); bf[2*j+1][1] = to_tf32(r3);
            }
            #pragma unroll
            for (int t = 0; t < 8; t++)
                MMA_TF32(o[t][0], o[t][1], o[t][2], o[t][3],
                         a0, a1, a2, a3, bf[t][0], bf[t][1]);
        }

        __syncthreads();
        const int pf = kt + 2;
        if (pf < NT) { load_KV(pf & 1, pf); CP_COMMIT(); }
    }

    // ---- write ctx ----
    const float inv0 = 1.0f / l0;
    const float inv1 = 1.0f / l1;
    const int qa = q0 + wid * 16 + gid;
    float* orow0 = O + (size_t)(b * SEQ + qa)     * DMODEL + h * HD;
    float* orow1 = O + (size_t)(b * SEQ + qa + 8) * DMODEL + h * HD;
    #pragma unroll
    for (int t = 0; t < 8; t++) {
        const int col = t * 8 + 2 * tg;
        float2 w0, w1;
        w0.x = o[t][0] * inv0; w0.y = o[t][1] * inv0;
        w1.x = o[t][2] * inv1; w1.y = o[t][3] * inv1;
        *(float2*)(orow0 + col) = w0;
        *(float2*)(orow1 + col) = w1;
    }
}

// ---------------------------------------------------------------------------
// Transpose helpers
// ---------------------------------------------------------------------------
__global__ __launch_bounds__(256)
void transpose_k(const float* __restrict__ in, float* __restrict__ out, int K, int N)
{
    __shared__ float tile[32][33];
    const int k0 = blockIdx.y * 32, n0 = blockIdx.x * 32;
    const int tx = threadIdx.x, ty = threadIdx.y;
    #pragma unroll
    for (int i = ty; i < 32; i += 8)
        tile[i][tx] = in[(size_t)(k0 + i) * N + n0 + tx];
    __syncthreads();
    #pragma unroll
    for (int i = ty; i < 32; i += 8)
        out[(size_t)(n0 + i) * K + k0 + tx] = tile[tx][i];
}

// V slice of fused qkv -> g_vt[bh][64][2048]
__global__ __launch_bounds__(256)
void transpose_vt(const float* __restrict__ qkv, float* __restrict__ vt)
{
    __shared__ float tile[32][33];
    const int s0 = blockIdx.x * 32;
    const int d0 = blockIdx.y * 32;
    const int bh = blockIdx.z;
    const int b = bh >> 4, h = bh & 15;
    const int tx = threadIdx.x, ty = threadIdx.y;
    const float* in = qkv + (size_t)b * SEQ * QLD + 2 * DMODEL + h * HD;
    float* out = vt + (size_t)bh * HD * SEQ;
    #pragma unroll
    for (int i = ty; i < 32; i += 8)
        tile[i][tx] = in[(size_t)(s0 + i) * QLD + d0 + tx];
    __syncthreads();
    #pragma unroll
    for (int i = ty; i < 32; i += 8)
        out[(size_t)(d0 + i) * SEQ + s0 + tx] = tile[tx][i];
}

__global__ void concat_bias(const float* a, const float* b, const float* c, float* out)
{
    int i = blockIdx.x * 256 + threadIdx.x;
    if (i < DMODEL)            out[i] = a[i];
    else if (i < 2 * DMODEL)   out[i] = b[i - DMODEL];
    else if (i < 3 * DMODEL)   out[i] = c[i - 2 * DMODEL];
}

// ---------------------------------------------------------------------------
// Fused residual add + LayerNorm over D=1024. One block (256 threads) per row.
// ---------------------------------------------------------------------------
__global__ __launch_bounds__(256)
void add_ln(const float* __restrict__ A, const float* __restrict__ Bv,
            const float* __restrict__ g, const float* __restrict__ be,
            float* __restrict__ out)
{
    const int row = blockIdx.x;
    const int tid = threadIdx.x;

    const float4 a4 = ((const float4*)(A  + (size_t)row * DMODEL))[tid];
    const float4 b4 = ((const float4*)(Bv + (size_t)row * DMODEL))[tid];
    float4 v;
    v.x = a4.x + b4.x; v.y = a4.y + b4.y; v.z = a4.z + b4.z; v.w = a4.w + b4.w;

    float s  = v.x + v.y + v.z + v.w;
    float ss = v.x*v.x + v.y*v.y + v.z*v.z + v.w*v.w;

    #pragma unroll
    for (int ofs = 16; ofs > 0; ofs >>= 1) {
        s  += __shfl_xor_sync(0xFFFFFFFFu, s,  ofs);
        ss += __shfl_xor_sync(0xFFFFFFFFu, ss, ofs);
    }

    __shared__ float shs[8], shss[8];
    const int w = tid >> 5;
    if ((tid & 31) == 0) { shs[w] = s; shss[w] = ss; }
    __syncthreads();
    if (tid < 32) {
        float s2  = (tid < 8) ? shs[tid]  : 0.f;
        float ss2 = (tid < 8) ? shss[tid] : 0.f;
        #pragma unroll
        for (int ofs = 4; ofs > 0; ofs >>= 1) {
            s2  += __shfl_xor_sync(0xFFFFFFFFu, s2,  ofs);
            ss2 += __shfl_xor_sync(0xFFFFFFFFu, ss2, ofs);
        }
        if (tid == 0) { shs[0] = s2; shss[0] = ss2; }
    }
    __syncthreads();

    const float mu  = shs[0]  * (1.f / DMODEL);
    const float var = shss[0] * (1.f / DMODEL) - mu * mu;
    const float inv = rsqrtf(var + 1e-5f);

    const float4 gv = ((const float4*)g)[tid];
    const float4 bb = ((const float4*)be)[tid];
    float4 o;
    o.x = (v.x - mu) * inv * gv.x + bb.x;
    o.y = (v.y - mu) * inv * gv.y + bb.y;
    o.z = (v.z - mu) * inv * gv.z + bb.z;
    o.w = (v.w - mu) * inv * gv.w + bb.w;
    ((float4*)(out + (size_t)row * DMODEL))[tid] = o;
}

// ---------------------------------------------------------------------------
// Launch
// ---------------------------------------------------------------------------
extern "C" void kernel_launch(void* const* d_in, const int* in_sizes, int n_in,
                              void* d_out, int out_size)
{
    const float* src  = (const float*)d_in[0];
    const float* Wq   = (const float*)d_in[1];
    const float* bq   = (const float*)d_in[2];
    const float* Wk   = (const float*)d_in[3];
    const float* bk   = (const float*)d_in[4];
    const float* Wv   = (const float*)d_in[5];
    const float* bv   = (const float*)d_in[6];
    const float* Wo   = (const float*)d_in[7];
    const float* bo   = (const float*)d_in[8];
    const float* W1   = (const float*)d_in[9];
    const float* b1   = (const float*)d_in[10];
    const float* W2   = (const float*)d_in[11];
    const float* b2   = (const float*)d_in[12];
    const float* ln1g = (const float*)d_in[13];
    const float* ln1b = (const float*)d_in[14];
    const float* ln2g = (const float*)d_in[15];
    const float* ln2b = (const float*)d_in[16];
    float* out = (float*)d_out;

    float *pqkv, *pvt, *pwqkvT, *pwoT, *pw1T, *pw2T, *pbqkv, *pctx, *ptmp, *px, *pff;
    cudaGetSymbolAddress((void**)&pqkv,   g_qkv);
    cudaGetSymbolAddress((void**)&pvt,    g_vt);
    cudaGetSymbolAddress((void**)&pwqkvT, g_wqkvT);
    cudaGetSymbolAddress((void**)&pwoT,   g_woT);
    cudaGetSymbolAddress((void**)&pw1T,   g_w1T);
    cudaGetSymbolAddress((void**)&pw2T,   g_w2T);
    cudaGetSymbolAddress((void**)&pbqkv,  g_bqkv);
    cudaGetSymbolAddress((void**)&pctx,   g_ctx);
    cudaGetSymbolAddress((void**)&ptmp,   g_tmp);
    cudaGetSymbolAddress((void**)&px,     g_x);
    cudaGetSymbolAddress((void**)&pff,    g_ff);

    cudaFuncSetAttribute(gemm_mma<false>, cudaFuncAttributeMaxDynamicSharedMemorySize, SMEM_DYN);
    cudaFuncSetAttribute(gemm_mma<true>,  cudaFuncAttributeMaxDynamicSharedMemorySize, SMEM_DYN);
    cudaFuncSetAttribute(flash_mma, cudaFuncAttributeMaxDynamicSharedMemorySize, ATT_SMEM);

    // Weight transposes (to K-major [N, K]) + fused qkv bias
    {
        dim3 blk(32, 8);
        transpose_k<<<dim3(32, 32),  blk>>>(Wq, pwqkvT,                       DMODEL, DMODEL);
        transpose_k<<<dim3(32, 32),  blk>>>(Wk, pwqkvT + DMODEL * DMODEL,     DMODEL, DMODEL);
        transpose_k<<<dim3(32, 32),  blk>>>(Wv, pwqkvT + 2 * DMODEL * DMODEL, DMODEL, DMODEL);
        transpose_k<<<dim3(32, 32),  blk>>>(Wo, pwoT,  DMODEL, DMODEL);
        transpose_k<<<dim3(128, 32), blk>>>(W1, pw1T,  DMODEL, DFF);
        transpose_k<<<dim3(32, 128), blk>>>(W2, pw2T,  DFF,    DMODEL);
        concat_bias<<<12, 256>>>(bq, bk, bv, pbqkv);
    }

    // Fused QKV projection: [4096,1024] @ [1024,3072] -> [4096,3072]
    gemm_mma<false><<<dim3(3 * DMODEL / 128, NTOK / 128), 256, SMEM_DYN>>>(
        src, pwqkvT, pbqkv, pqkv, NTOK, 3 * DMODEL, DMODEL);

    // V^T for attention PV operand
    transpose_vt<<<dim3(SEQ / 32, HD / 32, 32), dim3(32, 8)>>>(pqkv, pvt);

    // Tensor-core flash attention
    flash_mma<<<dim3(SEQ / 64, 2 * NHEAD), 128, ATT_SMEM>>>(pqkv, pvt, pctx);

    // Output projection + LN1
    gemm_mma<false><<<dim3(DMODEL / 128, NTOK / 128), 256, SMEM_DYN>>>(
        pctx, pwoT, bo, ptmp, NTOK, DMODEL, DMODEL);
    add_ln<<<NTOK, 256>>>(src, ptmp, ln1g, ln1b, px);

    // FFN
    gemm_mma<true><<<dim3(DFF / 128, NTOK / 128), 256, SMEM_DYN>>>(
        px, pw1T, b1, pff, NTOK, DFF, DMODEL);
    gemm_mma<false><<<dim3(DMODEL / 128, NTOK / 128), 256, SMEM_DYN>>>(
        pff, pw2T, b2, ptmp, NTOK, DMODEL, DFF);
    add_ln<<<NTOK, 256>>>(px, ptmp, ln2g, ln2b, out);
}

// round 6
// speedup vs baseline: 2.9611x; 1.0780x over previous
#include <cuda_runtime.h>
#include <cuda_bf16.h>
#include <math.h>
#include <stdint.h>

// Problem constants
#define NTOK   4096      // B*S = 2*2048
#define DMODEL 1024
#define DFF    4096
#define NHEAD  16
#define HD     64
#define SEQ    2048
#define QLD    (3 * DMODEL)   // fused qkv row stride

// ---------------------------------------------------------------------------
// Scratch (static device globals; no runtime allocation allowed)
// ---------------------------------------------------------------------------
__device__ __align__(16) float g_qkv [NTOK * 3 * DMODEL];    // fused q|k|v (tf32-rounded)
__device__ __align__(16) float g_vt  [32 * HD * SEQ];        // V^T per (b,h): [64][2048]
__device__ __align__(16) float g_srcr[NTOK * DMODEL];        // rounded src (QKV A operand)
__device__ __align__(16) float g_xr  [NTOK * DMODEL];        // rounded LN1 out (FFN1 A)
__device__ __align__(16) float g_wqkvT[3 * DMODEL * DMODEL]; // [3072,1024] K-major, rounded
__device__ __align__(16) float g_woT [DMODEL * DMODEL];
__device__ __align__(16) float g_w1T [DFF * DMODEL];
__device__ __align__(16) float g_w2T [DMODEL * DFF];
__device__ __align__(16) float g_bqkv[3 * DMODEL];
__device__ __align__(16) float g_ctx [NTOK * DMODEL];        // rounded flash output
__device__ __align__(16) float g_tmp [NTOK * DMODEL];
__device__ __align__(16) float g_x   [NTOK * DMODEL];
__device__ __align__(16) float g_ff  [NTOK * DFF];           // rounded FFN1 output

// ---------------------------------------------------------------------------
// PTX helpers (baseline sm_80+ features only — harness targets plain sm_103)
// ---------------------------------------------------------------------------
__device__ __forceinline__ uint32_t smem_u32(const void* p) {
    uint32_t a;
    asm("{ .reg .u64 t; cvta.to.shared.u64 t, %1; cvt.u32.u64 %0, t; }" : "=r"(a) : "l"(p));
    return a;
}
#define CP_ASYNC16(dst, src) \
    asm volatile("cp.async.cg.shared.global [%0], [%1], 16;" :: "r"(dst), "l"(src))
#define CP_COMMIT() asm volatile("cp.async.commit_group;" ::: "memory")
#define CP_WAIT(n)  asm volatile("cp.async.wait_group %0;" :: "n"(n) : "memory")

#define LDMATRIX_X4(r0, r1, r2, r3, addr) \
    asm volatile("ldmatrix.sync.aligned.m8n8.x4.shared.b16 {%0,%1,%2,%3}, [%4];" \
                 : "=r"(r0), "=r"(r1), "=r"(r2), "=r"(r3) : "r"(addr))

__device__ __forceinline__ uint32_t to_tf32f(float f) {
    uint32_t o;
    asm("cvt.rna.tf32.f32 %0, %1;" : "=r"(o) : "f"(f));
    return o;
}
__device__ __forceinline__ float roundf_tf32(float f) {
    return __uint_as_float(to_tf32f(f));
}

#define MMA_TF32(c0, c1, c2, c3, a0, a1, a2, a3, b0, b1) \
    asm volatile("mma.sync.aligned.m16n8k8.row.col.f32.tf32.tf32.f32 " \
                 "{%0,%1,%2,%3}, {%4,%5,%6,%7}, {%8,%9}, {%0,%1,%2,%3};" \
                 : "+f"(c0), "+f"(c1), "+f"(c2), "+f"(c3) \
                 : "r"(a0), "r"(a1), "r"(a2), "r"(a3), "r"(b0), "r"(b1))

// ---------------------------------------------------------------------------
// tf32 tensor-core GEMM:  C[M,N] = A[M,K] @ BT[N,K]^T + bias[N].
// Inputs MUST already be tf32-rounded (raw bits fed to mma — no in-loop cvt).
// ROUND: round outputs to tf32 (when C feeds another GEMM's A operand).
// ---------------------------------------------------------------------------
#define STAGES 4
#define STAGE_BYTES (2 * 128 * 32 * 4)
#define SMEM_DYN (STAGES * STAGE_BYTES)

template <bool RELU, bool ROUND>
__global__ __launch_bounds__(256, 1)
void gemm_mma(const float* __restrict__ A, const float* __restrict__ BT,
              const float* __restrict__ bias, float* __restrict__ C,
              int M, int N, int K)
{
    extern __shared__ char smem[];
    const uint32_t sbase = smem_u32(smem);
    const int tid  = threadIdx.x;
    const int wid  = tid >> 5;
    const int lane = tid & 31;
    const int warp_m = wid & 1;
    const int warp_n = wid >> 1;
    const int gid = lane >> 2;
    const int tg  = lane & 3;

    const int bm = blockIdx.y * 128;
    const int bn = blockIdx.x * 128;
    const int KT = K >> 5;

    const int lrow  = tid >> 1;
    const int lunit = (tid & 1) * 4;
    const float* Ag = A  + (size_t)(bm + lrow) * K + lunit * 4;
    const float* Bg = BT + (size_t)(bn + lrow) * K + lunit * 4;
    uint32_t lsw[4];
    #pragma unroll
    for (int i = 0; i < 4; i++) {
        uint32_t off = lrow * 128 + (lunit + i) * 16;
        lsw[i] = off ^ ((off >> 3) & 0x70);
    }

    uint32_t a_rel[4], a_xr[4];
    #pragma unroll
    for (int i = 0; i < 4; i++) {
        int r = warp_m * 64 + i * 16 + (lane & 7) + ((lane >> 3) & 1) * 8;
        a_rel[i] = r * 128;
        a_xr[i]  = (r & 7) << 4;
    }
    const uint32_t a_kb = ((lane >> 4) & 1) * 16;
    uint32_t b_rel[2], b_xr[2];
    #pragma unroll
    for (int j = 0; j < 2; j++) {
        int r = warp_n * 32 + j * 16 + (lane & 7) + ((lane >> 4) & 1) * 8;
        b_rel[j] = r * 128;
        b_xr[j]  = (r & 7) << 4;
    }
    const uint32_t b_kb = ((lane >> 3) & 1) * 16;

    float acc[4][4][4];
    #pragma unroll
    for (int i = 0; i < 4; i++)
        #pragma unroll
        for (int t = 0; t < 4; t++)
            #pragma unroll
            for (int r = 0; r < 4; r++) acc[i][t][r] = 0.f;

    auto load_tile = [&](int s, int kt) {
        const uint32_t sA = sbase + s * STAGE_BYTES;
        const uint32_t sB = sA + 16384;
        const float* ar = Ag + kt * 32;
        const float* br = Bg + kt * 32;
        #pragma unroll
        for (int i = 0; i < 4; i++) CP_ASYNC16(sA + lsw[i], ar + i * 4);
        #pragma unroll
        for (int i = 0; i < 4; i++) CP_ASYNC16(sB + lsw[i], br + i * 4);
    };

    #pragma unroll
    for (int s = 0; s < STAGES - 1; s++) { load_tile(s, s); CP_COMMIT(); }

    for (int kt = 0; kt < KT; kt++) {
        const int cur = kt & (STAGES - 1);
        CP_WAIT(STAGES - 2);
        __syncthreads();

        const int pf = kt + STAGES - 1;
        if (pf < KT) load_tile(pf & (STAGES - 1), pf);
        CP_COMMIT();

        const uint32_t sA = sbase + cur * STAGE_BYTES;
        const uint32_t sB = sA + 16384;

        #pragma unroll
        for (int ks = 0; ks < 4; ks++) {
            const uint32_t kso = ks * 32;
            uint32_t af[4][4];
            #pragma unroll
            for (int i = 0; i < 4; i++) {
                uint32_t addr = sA + ((a_rel[i] + a_kb + kso) ^ a_xr[i]);
                LDMATRIX_X4(af[i][0], af[i][1], af[i][2], af[i][3], addr);
            }
            uint32_t bf[4][2];
            #pragma unroll
            for (int j = 0; j < 2; j++) {
                uint32_t r0, r1, r2, r3;
                uint32_t addr = sB + ((b_rel[j] + b_kb + kso) ^ b_xr[j]);
                LDMATRIX_X4(r0, r1, r2, r3, addr);
                bf[2*j+0][0] = r0; bf[2*j+0][1] = r1;
                bf[2*j+1][0] = r2; bf[2*j+1][1] = r3;
            }
            #pragma unroll
            for (int i = 0; i < 4; i++)
                #pragma unroll
                for (int t = 0; t < 4; t++)
                    MMA_TF32(acc[i][t][0], acc[i][t][1], acc[i][t][2], acc[i][t][3],
                             af[i][0], af[i][1], af[i][2], af[i][3],
                             bf[t][0], bf[t][1]);
        }
        __syncthreads();
    }

    #pragma unroll
    for (int i = 0; i < 4; i++) {
        const int row0 = bm + warp_m * 64 + i * 16 + gid;
        #pragma unroll
        for (int t = 0; t < 4; t++) {
            const int col = bn + warp_n * 32 + t * 8 + 2 * tg;
            const float2 bv = *(const float2*)(bias + col);
            float2 v0, v1;
            v0.x = acc[i][t][0] + bv.x; v0.y = acc[i][t][1] + bv.y;
            v1.x = acc[i][t][2] + bv.x; v1.y = acc[i][t][3] + bv.y;
            if (RELU) {
                v0.x = fmaxf(v0.x, 0.f); v0.y = fmaxf(v0.y, 0.f);
                v1.x = fmaxf(v1.x, 0.f); v1.y = fmaxf(v1.y, 0.f);
            }
            if (ROUND) {
                v0.x = roundf_tf32(v0.x); v0.y = roundf_tf32(v0.y);
                v1.x = roundf_tf32(v1.x); v1.y = roundf_tf32(v1.y);
            }
            *(float2*)(C + (size_t)row0 * N + col)       = v0;
            *(float2*)(C + (size_t)(row0 + 8) * N + col) = v1;
        }
    }
}

// ---------------------------------------------------------------------------
// Tensor-core flash attention (tf32 mma). 64 queries x 1 head per block.
// Q/K/V already tf32-rounded; raw bits feed mma. Output rounded (feeds O-proj).
// ---------------------------------------------------------------------------
#define ATT_SMEM 65536

__global__ __launch_bounds__(128, 1)
void flash_mma(const float* __restrict__ QKV, const float* __restrict__ VT,
               float* __restrict__ O)
{
    extern __shared__ char smem[];
    const uint32_t sbase = smem_u32(smem);
    const int tid  = threadIdx.x;
    const int wid  = tid >> 5;
    const int lane = tid & 31;
    const int gid  = lane >> 2;
    const int tg   = lane & 3;

    const int bh = blockIdx.y;
    const int b  = bh >> 4;
    const int h  = bh & 15;
    const int q0 = blockIdx.x * 64;

    const float* Qg  = QKV + (size_t)b * SEQ * QLD + h * HD;
    const float* Kg  = Qg + DMODEL;
    const float* VTg = VT + (size_t)bh * HD * SEQ;

    const uint32_t qreg = sbase + 32768;

    const int lrow = tid >> 1;
    const int lu0  = (tid & 1) * 8;
    uint32_t lsw[8];
    #pragma unroll
    for (int i = 0; i < 8; i++) {
        int u = lu0 + i;
        uint32_t off = lrow * 128 + (u & 7) * 16;
        lsw[i] = (u >> 3) * 8192 + (off ^ ((off >> 3) & 0x70));
    }

    uint32_t aq_rel, aq_xr;
    {
        int r = wid * 16 + (lane & 7) + ((lane >> 3) & 1) * 8;
        aq_rel = r * 128;
        aq_xr  = (r & 7) << 4;
    }
    const uint32_t a_kb = ((lane >> 4) & 1) * 16;
    uint32_t b_rel[4], b_xr[4];
    #pragma unroll
    for (int j = 0; j < 4; j++) {
        int r = j * 16 + (lane & 7) + ((lane >> 4) & 1) * 8;
        b_rel[j] = r * 128;
        b_xr[j]  = (r & 7) << 4;
    }
    const uint32_t b_kb = ((lane >> 3) & 1) * 16;

    auto load_KV = [&](int stage, int kt) {
        const uint32_t sK = sbase + stage * 32768;
        const uint32_t sV = sK + 16384;
        const float* kr = Kg  + (size_t)(kt * 64 + lrow) * QLD + lu0 * 4;
        const float* vr = VTg + (size_t)lrow * SEQ + kt * 64 + lu0 * 4;
        #pragma unroll
        for (int i = 0; i < 8; i++) CP_ASYNC16(sK + lsw[i], kr + i * 4);
        #pragma unroll
        for (int i = 0; i < 8; i++) CP_ASYNC16(sV + lsw[i], vr + i * 4);
    };

    {
        const float* qr = Qg + (size_t)(q0 + lrow) * QLD + lu0 * 4;
        #pragma unroll
        for (int i = 0; i < 8; i++) CP_ASYNC16(qreg + lsw[i], qr + i * 4);
        load_KV(0, 0);
        CP_COMMIT();
        CP_WAIT(0);
        __syncthreads();
    }

    uint32_t qf[8][4];
    #pragma unroll
    for (int c = 0; c < 2; c++)
        #pragma unroll
        for (int ks = 0; ks < 4; ks++) {
            uint32_t addr = qreg + c * 8192 + ((aq_rel + a_kb + ks * 32) ^ aq_xr);
            LDMATRIX_X4(qf[c*4+ks][0], qf[c*4+ks][1], qf[c*4+ks][2], qf[c*4+ks][3], addr);
        }
    __syncthreads();

    const int NT = SEQ / 64;
    load_KV(1, 1);
    CP_COMMIT();

    float o[8][4];
    #pragma unroll
    for (int t = 0; t < 8; t++)
        #pragma unroll
        for (int r = 0; r < 4; r++) o[t][r] = 0.f;
    float m0 = -1e30f, m1 = -1e30f, l0 = 0.f, l1 = 0.f;

    for (int kt = 0; kt < NT; kt++) {
        if (kt < NT - 1) { CP_WAIT(1); } else { CP_WAIT(0); }
        __syncthreads();
        const uint32_t sK = sbase + (kt & 1) * 32768;
        const uint32_t sV = sK + 16384;

        // ---- S = Q @ K^T ----
        float s[8][4];
        #pragma unroll
        for (int t = 0; t < 8; t++)
            #pragma unroll
            for (int r = 0; r < 4; r++) s[t][r] = 0.f;

        #pragma unroll
        for (int c = 0; c < 2; c++)
            #pragma unroll
            for (int ks = 0; ks < 4; ks++) {
                uint32_t bf[8][2];
                #pragma unroll
                for (int j = 0; j < 4; j++) {
                    uint32_t r0, r1, r2, r3;
                    uint32_t addr = sK + c * 8192 + ((b_rel[j] + b_kb + ks * 32) ^ b_xr[j]);
                    LDMATRIX_X4(r0, r1, r2, r3, addr);
                    bf[2*j+0][0] = r0; bf[2*j+0][1] = r1;
                    bf[2*j+1][0] = r2; bf[2*j+1][1] = r3;
                }
                const uint32_t* aq = qf[c*4+ks];
                #pragma unroll
                for (int t = 0; t < 8; t++)
                    MMA_TF32(s[t][0], s[t][1], s[t][2], s[t][3],
                             aq[0], aq[1], aq[2], aq[3], bf[t][0], bf[t][1]);
            }

        // ---- online softmax ----
        float tmax0 = -1e30f, tmax1 = -1e30f;
        #pragma unroll
        for (int t = 0; t < 8; t++) {
            s[t][0] *= 0.125f; s[t][1] *= 0.125f; s[t][2] *= 0.125f; s[t][3] *= 0.125f;
            tmax0 = fmaxf(tmax0, fmaxf(s[t][0], s[t][1]));
            tmax1 = fmaxf(tmax1, fmaxf(s[t][2], s[t][3]));
        }
        tmax0 = fmaxf(tmax0, __shfl_xor_sync(0xffffffffu, tmax0, 1));
        tmax0 = fmaxf(tmax0, __shfl_xor_sync(0xffffffffu, tmax0, 2));
        tmax1 = fmaxf(tmax1, __shfl_xor_sync(0xffffffffu, tmax1, 1));
        tmax1 = fmaxf(tmax1, __shfl_xor_sync(0xffffffffu, tmax1, 2));

        const float mnew0 = fmaxf(m0, tmax0);
        const float mnew1 = fmaxf(m1, tmax1);
        const float corr0 = __expf(m0 - mnew0);
        const float corr1 = __expf(m1 - mnew1);

        float rs0 = 0.f, rs1 = 0.f;
        #pragma unroll
        for (int t = 0; t < 8; t++) {
            s[t][0] = __expf(s[t][0] - mnew0);
            s[t][1] = __expf(s[t][1] - mnew0);
            s[t][2] = __expf(s[t][2] - mnew1);
            s[t][3] = __expf(s[t][3] - mnew1);
            rs0 += s[t][0] + s[t][1];
            rs1 += s[t][2] + s[t][3];
        }
        rs0 += __shfl_xor_sync(0xffffffffu, rs0, 1);
        rs0 += __shfl_xor_sync(0xffffffffu, rs0, 2);
        rs1 += __shfl_xor_sync(0xffffffffu, rs1, 1);
        rs1 += __shfl_xor_sync(0xffffffffu, rs1, 2);

        l0 = l0 * corr0 + rs0;
        l1 = l1 * corr1 + rs1;
        #pragma unroll
        for (int t = 0; t < 8; t++) {
            o[t][0] *= corr0; o[t][1] *= corr0;
            o[t][2] *= corr1; o[t][3] *= corr1;
        }
        m0 = mnew0; m1 = mnew1;

        // ---- ctx += P @ V ----
        #pragma unroll
        for (int ks = 0; ks < 8; ks++) {
            const int src0 = tg >> 1, src1 = src0 + 2;
            float v00 = __shfl_sync(0xffffffffu, s[ks][0], src0, 4);
            float v01 = __shfl_sync(0xffffffffu, s[ks][1], src0, 4);
            float v20 = __shfl_sync(0xffffffffu, s[ks][0], src1, 4);
            float v21 = __shfl_sync(0xffffffffu, s[ks][1], src1, 4);
            float v10 = __shfl_sync(0xffffffffu, s[ks][2], src0, 4);
            float v11 = __shfl_sync(0xffffffffu, s[ks][3], src0, 4);
            float v30 = __shfl_sync(0xffffffffu, s[ks][2], src1, 4);
            float v31 = __shfl_sync(0xffffffffu, s[ks][3], src1, 4);
            const bool oddc = (tg & 1);
            uint32_t a0 = to_tf32f(oddc ? v01 : v00);
            uint32_t a1 = to_tf32f(oddc ? v11 : v10);
            uint32_t a2 = to_tf32f(oddc ? v21 : v20);
            uint32_t a3 = to_tf32f(oddc ? v31 : v30);

            uint32_t bf[8][2];
            const uint32_t vbase = sV + (ks >> 2) * 8192;
            const uint32_t kso = (ks & 3) * 32;
            #pragma unroll
            for (int j = 0; j < 4; j++) {
                uint32_t r0, r1, r2, r3;
                uint32_t addr = vbase + ((b_rel[j] + b_kb + kso) ^ b_xr[j]);
                LDMATRIX_X4(r0, r1, r2, r3, addr);
                bf[2*j+0][0] = r0; bf[2*j+0][1] = r1;
                bf[2*j+1][0] = r2; bf[2*j+1][1] = r3;
            }
            #pragma unroll
            for (int t = 0; t < 8; t++)
                MMA_TF32(o[t][0], o[t][1], o[t][2], o[t][3],
                         a0, a1, a2, a3, bf[t][0], bf[t][1]);
        }

        __syncthreads();
        const int pf = kt + 2;
        if (pf < NT) { load_KV(pf & 1, pf); CP_COMMIT(); }
    }

    // ---- write ctx (tf32-rounded: feeds O-projection A operand) ----
    const float inv0 = 1.0f / l0;
    const float inv1 = 1.0f / l1;
    const int qa = q0 + wid * 16 + gid;
    float* orow0 = O + (size_t)(b * SEQ + qa)     * DMODEL + h * HD;
    float* orow1 = O + (size_t)(b * SEQ + qa + 8) * DMODEL + h * HD;
    #pragma unroll
    for (int t = 0; t < 8; t++) {
        const int col = t * 8 + 2 * tg;
        float2 w0, w1;
        w0.x = roundf_tf32(o[t][0] * inv0); w0.y = roundf_tf32(o[t][1] * inv0);
        w1.x = roundf_tf32(o[t][2] * inv1); w1.y = roundf_tf32(o[t][3] * inv1);
        *(float2*)(orow0 + col) = w0;
        *(float2*)(orow1 + col) = w1;
    }
}

// ---------------------------------------------------------------------------
// Transpose helpers (weight transposes round to tf32 — they feed mma B)
// ---------------------------------------------------------------------------
__global__ __launch_bounds__(256)
void transpose_k(const float* __restrict__ in, float* __restrict__ out, int K, int N)
{
    __shared__ float tile[32][33];
    const int k0 = blockIdx.y * 32, n0 = blockIdx.x * 32;
    const int tx = threadIdx.x, ty = threadIdx.y;
    #pragma unroll
    for (int i = ty; i < 32; i += 8)
        tile[i][tx] = in[(size_t)(k0 + i) * N + n0 + tx];
    __syncthreads();
    #pragma unroll
    for (int i = ty; i < 32; i += 8)
        out[(size_t)(n0 + i) * K + k0 + tx] = roundf_tf32(tile[tx][i]);
}

// V slice of fused qkv -> g_vt[bh][64][2048] (input already rounded)
__global__ __launch_bounds__(256)
void transpose_vt(const float* __restrict__ qkv, float* __restrict__ vt)
{
    __shared__ float tile[32][33];
    const int s0 = blockIdx.x * 32;
    const int d0 = blockIdx.y * 32;
    const int bh = blockIdx.z;
    const int b = bh >> 4, h = bh & 15;
    const int tx = threadIdx.x, ty = threadIdx.y;
    const float* in = qkv + (size_t)b * SEQ * QLD + 2 * DMODEL + h * HD;
    float* out = vt + (size_t)bh * HD * SEQ;
    #pragma unroll
    for (int i = ty; i < 32; i += 8)
        tile[i][tx] = in[(size_t)(s0 + i) * QLD + d0 + tx];
    __syncthreads();
    #pragma unroll
    for (int i = ty; i < 32; i += 8)
        out[(size_t)(d0 + i) * SEQ + s0 + tx] = tile[tx][i];
}

__global__ void concat_bias(const float* a, const float* b, const float* c, float* out)
{
    int i = blockIdx.x * 256 + threadIdx.x;
    if (i < DMODEL)            out[i] = a[i];
    else if (i < 2 * DMODEL)   out[i] = b[i - DMODEL];
    else if (i < 3 * DMODEL)   out[i] = c[i - 2 * DMODEL];
}

// Rounded copy: out[i] = tf32(in[i]). Vectorized float4.
__global__ __launch_bounds__(256)
void round_copy(const float* __restrict__ in, float* __restrict__ out, int n4)
{
    int i = blockIdx.x * 256 + threadIdx.x;
    if (i < n4) {
        float4 v = ((const float4*)in)[i];
        v.x = roundf_tf32(v.x); v.y = roundf_tf32(v.y);
        v.z = roundf_tf32(v.z); v.w = roundf_tf32(v.w);
        ((float4*)out)[i] = v;
    }
}

// ---------------------------------------------------------------------------
// Fused residual add + LayerNorm over D=1024. One block (256 threads) per row.
// Optionally writes a tf32-rounded second copy (for downstream GEMM A operand).
// ---------------------------------------------------------------------------
__global__ __launch_bounds__(256)
void add_ln(const float* __restrict__ A, const float* __restrict__ Bv,
            const float* __restrict__ g, const float* __restrict__ be,
            float* __restrict__ out, float* __restrict__ out_r)
{
    const int row = blockIdx.x;
    const int tid = threadIdx.x;

    const float4 a4 = ((const float4*)(A  + (size_t)row * DMODEL))[tid];
    const float4 b4 = ((const float4*)(Bv + (size_t)row * DMODEL))[tid];
    float4 v;
    v.x = a4.x + b4.x; v.y = a4.y + b4.y; v.z = a4.z + b4.z; v.w = a4.w + b4.w;

    float s  = v.x + v.y + v.z + v.w;
    float ss = v.x*v.x + v.y*v.y + v.z*v.z + v.w*v.w;

    #pragma unroll
    for (int ofs = 16; ofs > 0; ofs >>= 1) {
        s  += __shfl_xor_sync(0xFFFFFFFFu, s,  ofs);
        ss += __shfl_xor_sync(0xFFFFFFFFu, ss, ofs);
    }

    __shared__ float shs[8], shss[8];
    const int w = tid >> 5;
    if ((tid & 31) == 0) { shs[w] = s; shss[w] = ss; }
    __syncthreads();
    if (tid < 32) {
        float s2  = (tid < 8) ? shs[tid]  : 0.f;
        float ss2 = (tid < 8) ? shss[tid] : 0.f;
        #pragma unroll
        for (int ofs = 4; ofs > 0; ofs >>= 1) {
            s2  += __shfl_xor_sync(0xFFFFFFFFu, s2,  ofs);
            ss2 += __shfl_xor_sync(0xFFFFFFFFu, ss2, ofs);
        }
        if (tid == 0) { shs[0] = s2; shss[0] = ss2; }
    }
    __syncthreads();

    const float mu  = shs[0]  * (1.f / DMODEL);
    const float var = shss[0] * (1.f / DMODEL) - mu * mu;
    const float inv = rsqrtf(var + 1e-5f);

    const float4 gv = ((const float4*)g)[tid];
    const float4 bb = ((const float4*)be)[tid];
    float4 o;
    o.x = (v.x - mu) * inv * gv.x + bb.x;
    o.y = (v.y - mu) * inv * gv.y + bb.y;
    o.z = (v.z - mu) * inv * gv.z + bb.z;
    o.w = (v.w - mu) * inv * gv.w + bb.w;
    ((float4*)(out + (size_t)row * DMODEL))[tid] = o;
    if (out_r) {
        float4 r;
        r.x = roundf_tf32(o.x); r.y = roundf_tf32(o.y);
        r.z = roundf_tf32(o.z); r.w = roundf_tf32(o.w);
        ((float4*)(out_r + (size_t)row * DMODEL))[tid] = r;
    }
}

// ---------------------------------------------------------------------------
// Launch
// ---------------------------------------------------------------------------
extern "C" void kernel_launch(void* const* d_in, const int* in_sizes, int n_in,
                              void* d_out, int out_size)
{
    const float* src  = (const float*)d_in[0];
    const float* Wq   = (const float*)d_in[1];
    const float* bq   = (const float*)d_in[2];
    const float* Wk   = (const float*)d_in[3];
    const float* bk   = (const float*)d_in[4];
    const float* Wv   = (const float*)d_in[5];
    const float* bv   = (const float*)d_in[6];
    const float* Wo   = (const float*)d_in[7];
    const float* bo   = (const float*)d_in[8];
    const float* W1   = (const float*)d_in[9];
    const float* b1   = (const float*)d_in[10];
    const float* W2   = (const float*)d_in[11];
    const float* b2   = (const float*)d_in[12];
    const float* ln1g = (const float*)d_in[13];
    const float* ln1b = (const float*)d_in[14];
    const float* ln2g = (const float*)d_in[15];
    const float* ln2b = (const float*)d_in[16];
    float* out = (float*)d_out;

    float *pqkv, *pvt, *psrcr, *pxr, *pwqkvT, *pwoT, *pw1T, *pw2T, *pbqkv,
          *pctx, *ptmp, *px, *pff;
    cudaGetSymbolAddress((void**)&pqkv,   g_qkv);
    cudaGetSymbolAddress((void**)&pvt,    g_vt);
    cudaGetSymbolAddress((void**)&psrcr,  g_srcr);
    cudaGetSymbolAddress((void**)&pxr,    g_xr);
    cudaGetSymbolAddress((void**)&pwqkvT, g_wqkvT);
    cudaGetSymbolAddress((void**)&pwoT,   g_woT);
    cudaGetSymbolAddress((void**)&pw1T,   g_w1T);
    cudaGetSymbolAddress((void**)&pw2T,   g_w2T);
    cudaGetSymbolAddress((void**)&pbqkv,  g_bqkv);
    cudaGetSymbolAddress((void**)&pctx,   g_ctx);
    cudaGetSymbolAddress((void**)&ptmp,   g_tmp);
    cudaGetSymbolAddress((void**)&px,     g_x);
    cudaGetSymbolAddress((void**)&pff,    g_ff);

    cudaFuncSetAttribute((const void*)gemm_mma<false,false>, cudaFuncAttributeMaxDynamicSharedMemorySize, SMEM_DYN);
    cudaFuncSetAttribute((const void*)gemm_mma<false,true>,  cudaFuncAttributeMaxDynamicSharedMemorySize, SMEM_DYN);
    cudaFuncSetAttribute((const void*)gemm_mma<true,true>,   cudaFuncAttributeMaxDynamicSharedMemorySize, SMEM_DYN);
    cudaFuncSetAttribute((const void*)flash_mma, cudaFuncAttributeMaxDynamicSharedMemorySize, ATT_SMEM);

    // Pre-rounded inputs + weight transposes (to K-major [N,K], tf32-rounded)
    {
        dim3 blk(32, 8);
        round_copy<<<(NTOK * DMODEL / 4 + 255) / 256, 256>>>(src, psrcr, NTOK * DMODEL / 4);
        transpose_k<<<dim3(32, 32),  blk>>>(Wq, pwqkvT,                       DMODEL, DMODEL);
        transpose_k<<<dim3(32, 32),  blk>>>(Wk, pwqkvT + DMODEL * DMODEL,     DMODEL, DMODEL);
        transpose_k<<<dim3(32, 32),  blk>>>(Wv, pwqkvT + 2 * DMODEL * DMODEL, DMODEL, DMODEL);
        transpose_k<<<dim3(32, 32),  blk>>>(Wo, pwoT,  DMODEL, DMODEL);
        transpose_k<<<dim3(128, 32), blk>>>(W1, pw1T,  DMODEL, DFF);
        transpose_k<<<dim3(32, 128), blk>>>(W2, pw2T,  DFF,    DMODEL);
        concat_bias<<<12, 256>>>(bq, bk, bv, pbqkv);
    }

    // Fused QKV projection (output rounded: feeds attention)
    gemm_mma<false, true><<<dim3(3 * DMODEL / 128, NTOK / 128), 256, SMEM_DYN>>>(
        psrcr, pwqkvT, pbqkv, pqkv, NTOK, 3 * DMODEL, DMODEL);

    // V^T for attention PV operand
    transpose_vt<<<dim3(SEQ / 32, HD / 32, 32), dim3(32, 8)>>>(pqkv, pvt);

    // Tensor-core flash attention (output rounded: feeds O-proj)
    flash_mma<<<dim3(SEQ / 64, 2 * NHEAD), 128, ATT_SMEM>>>(pqkv, pvt, pctx);

    // Output projection (full-precision out: feeds residual) + LN1
    gemm_mma<false, false><<<dim3(DMODEL / 128, NTOK / 128), 256, SMEM_DYN>>>(
        pctx, pwoT, bo, ptmp, NTOK, DMODEL, DMODEL);
    add_ln<<<NTOK, 256>>>(src, ptmp, ln1g, ln1b, px, pxr);

    // FFN
    gemm_mma<true, true><<<dim3(DFF / 128, NTOK / 128), 256, SMEM_DYN>>>(
        pxr, pw1T, b1, pff, NTOK, DFF, DMODEL);
    gemm_mma<false, false><<<dim3(DMODEL / 128, NTOK / 128), 256, SMEM_DYN>>>(
        pff, pw2T, b2, ptmp, NTOK, DMODEL, DFF);
    add_ln<<<NTOK, 256>>>(px, ptmp, ln2g, ln2b, out, (float*)nullptr);
}